// round 1
// baseline (speedup 1.0000x reference)
#include <cuda_runtime.h>
#include <cuda_bf16.h>

// Problem constants
#define BATCH 4
#define SEQ   2048
#define DMODEL 1024
#define NHEAD 16
#define HDIM  64
#define SCALE 0.25f
// q-tile rows per attention CTA
#define QT 64

// Scratch: Q/K/V in [B, H, L, HD] layout (32 MB each, static device arrays)
__device__ float g_Q[(size_t)BATCH * NHEAD * SEQ * HDIM];
__device__ float g_K[(size_t)BATCH * NHEAD * SEQ * HDIM];
__device__ float g_V[(size_t)BATCH * NHEAD * SEQ * HDIM];

// ---------------------------------------------------------------------------
// Projection GEMM: out[l, d] = dot(X[l, :], W[d, :]) + bias[d]
// Tile 64x64, 256 threads, 4x4 microtile. blockIdx.z selects Q/K/V.
// Output written directly in [B, H, L, HD] layout.
// ---------------------------------------------------------------------------
__global__ __launch_bounds__(256) void proj_kernel(
    const float* __restrict__ X,
    const float* __restrict__ Wq, const float* __restrict__ bq,
    const float* __restrict__ Wk, const float* __restrict__ bk,
    const float* __restrict__ Wv, const float* __restrict__ bv)
{
    const int which = blockIdx.z;
    const float* __restrict__ W    = (which == 0) ? Wq : (which == 1) ? Wk : Wv;
    const float* __restrict__ bias = (which == 0) ? bq : (which == 1) ? bk : bv;
    float* __restrict__ out        = (which == 0) ? g_Q : (which == 1) ? g_K : g_V;

    const int rowBase = blockIdx.x * 64;   // over B*L = 8192
    const int colBase = blockIdx.y * 64;   // over D = 1024

    __shared__ float As[16][65];  // [k][row]
    __shared__ float Bs[16][65];  // [k][col]

    const int tid = threadIdx.x;
    const int tx = tid & 15;
    const int ty = tid >> 4;

    float acc[4][4] = {};

    const int lr  = tid >> 2;         // 0..63 (row within tile for loads)
    const int lkq = (tid & 3) * 4;    // 0,4,8,12 (k within step)

    for (int k0 = 0; k0 < DMODEL; k0 += 16) {
        // Load X tile (64 rows x 16 k) and W tile (64 cols x 16 k)
        float4 va = *(const float4*)&X[(size_t)(rowBase + lr) * DMODEL + k0 + lkq];
        As[lkq + 0][lr] = va.x; As[lkq + 1][lr] = va.y;
        As[lkq + 2][lr] = va.z; As[lkq + 3][lr] = va.w;
        float4 vb = *(const float4*)&W[(size_t)(colBase + lr) * DMODEL + k0 + lkq];
        Bs[lkq + 0][lr] = vb.x; Bs[lkq + 1][lr] = vb.y;
        Bs[lkq + 2][lr] = vb.z; Bs[lkq + 3][lr] = vb.w;
        __syncthreads();

        #pragma unroll
        for (int k = 0; k < 16; ++k) {
            float a[4], b[4];
            #pragma unroll
            for (int i = 0; i < 4; ++i) a[i] = As[k][ty * 4 + i];
            #pragma unroll
            for (int j = 0; j < 4; ++j) b[j] = Bs[k][tx + 16 * j];
            #pragma unroll
            for (int i = 0; i < 4; ++i)
                #pragma unroll
                for (int j = 0; j < 4; ++j)
                    acc[i][j] += a[i] * b[j];
        }
        __syncthreads();
    }

    // Write in [B, H, L, HD] layout
    #pragma unroll
    for (int i = 0; i < 4; ++i) {
        const int row = rowBase + ty * 4 + i;       // global token index in [0, B*L)
        const int b   = row / SEQ;
        const int s   = row % SEQ;
        #pragma unroll
        for (int j = 0; j < 4; ++j) {
            const int col = colBase + tx + 16 * j;  // dim index in [0, D)
            const int h   = col / HDIM;
            const int hd  = col % HDIM;
            const size_t o = (((size_t)b * NHEAD + h) * SEQ + s) * HDIM + hd;
            out[o] = acc[i][j] + bias[col];
        }
    }
}

// ---------------------------------------------------------------------------
// Flash-attention (causal, fp32, online softmax).
// Grid: x = SEQ/QT q-tiles (heavy-first), y = B*H.
// 256 threads, 4x4 microtile; S tile 64x64; P aliases K smem buffer.
// ---------------------------------------------------------------------------
__global__ __launch_bounds__(256) void attn_kernel(float* __restrict__ out)
{
    extern __shared__ float smem[];
    float (*Qs)[65]  = (float(*)[65])smem;               // [64][65]
    float (*KPs)[65] = (float(*)[65])(smem + 64 * 65);   // K tile, then P tile
    float (*Vs)[65]  = (float(*)[65])(smem + 2 * 64 * 65);

    const int bh = blockIdx.y;                   // 0..63
    const int b  = bh >> 4;
    const int h  = bh & 15;
    const int qi = (SEQ / QT - 1) - blockIdx.x;  // heavy q-tiles first

    const float* __restrict__ Qp = g_Q + (((size_t)bh * SEQ) + (size_t)qi * QT) * HDIM;
    const float* __restrict__ Kb = g_K + (size_t)bh * SEQ * HDIM;
    const float* __restrict__ Vb = g_V + (size_t)bh * SEQ * HDIM;

    const int tid = threadIdx.x;
    const int tx = tid & 15;
    const int ty = tid >> 4;

    // Load Q tile: 64 rows x 64 dims = 1024 float4
    #pragma unroll
    for (int it = 0; it < 4; ++it) {
        const int idx = tid + 256 * it;
        const int r  = idx >> 4;
        const int cq = (idx & 15) * 4;
        float4 v = *(const float4*)(Qp + r * HDIM + cq);
        Qs[r][cq + 0] = v.x; Qs[r][cq + 1] = v.y;
        Qs[r][cq + 2] = v.z; Qs[r][cq + 3] = v.w;
    }

    float oacc[4][4] = {};
    float mrun[4], lrun[4];
    #pragma unroll
    for (int i = 0; i < 4; ++i) { mrun[i] = -1e30f; lrun[i] = 0.0f; }

    __syncthreads();

    for (int jb = 0; jb <= qi; ++jb) {
        // Load K and V tiles for this key block
        const float* Kp = Kb + (size_t)jb * QT * HDIM;
        const float* Vp = Vb + (size_t)jb * QT * HDIM;
        #pragma unroll
        for (int it = 0; it < 4; ++it) {
            const int idx = tid + 256 * it;
            const int r  = idx >> 4;
            const int cq = (idx & 15) * 4;
            float4 kv = *(const float4*)(Kp + r * HDIM + cq);
            KPs[r][cq + 0] = kv.x; KPs[r][cq + 1] = kv.y;
            KPs[r][cq + 2] = kv.z; KPs[r][cq + 3] = kv.w;
            float4 vv = *(const float4*)(Vp + r * HDIM + cq);
            Vs[r][cq + 0] = vv.x; Vs[r][cq + 1] = vv.y;
            Vs[r][cq + 2] = vv.z; Vs[r][cq + 3] = vv.w;
        }
        __syncthreads();

        // S = Q K^T (4x4 microtile per thread)
        float s[4][4] = {};
        #pragma unroll 8
        for (int d = 0; d < HDIM; ++d) {
            float qv[4], kv[4];
            #pragma unroll
            for (int i = 0; i < 4; ++i) qv[i] = Qs[ty * 4 + i][d];
            #pragma unroll
            for (int j = 0; j < 4; ++j) kv[j] = KPs[tx + 16 * j][d];
            #pragma unroll
            for (int i = 0; i < 4; ++i)
                #pragma unroll
                for (int j = 0; j < 4; ++j)
                    s[i][j] += qv[i] * kv[j];
        }
        __syncthreads();  // done reading K; KPs buffer will hold P

        // Scale + causal mask on the diagonal block
        const bool diag = (jb == qi);
        #pragma unroll
        for (int i = 0; i < 4; ++i) {
            const int r = ty * 4 + i;
            #pragma unroll
            for (int j = 0; j < 4; ++j) {
                const int c = tx + 16 * j;
                s[i][j] = (diag && c > r) ? -1e30f : s[i][j] * SCALE;
            }
        }

        // Online softmax (row reduction over 16 tx lanes)
        #pragma unroll
        for (int i = 0; i < 4; ++i) {
            float rm = fmaxf(fmaxf(s[i][0], s[i][1]), fmaxf(s[i][2], s[i][3]));
            #pragma unroll
            for (int off = 8; off >= 1; off >>= 1)
                rm = fmaxf(rm, __shfl_xor_sync(0xffffffffu, rm, off));
            const float mnew = fmaxf(mrun[i], rm);
            const float corr = __expf(mrun[i] - mnew);
            lrun[i] *= corr;
            #pragma unroll
            for (int j = 0; j < 4; ++j) oacc[i][j] *= corr;
            float psum = 0.0f;
            #pragma unroll
            for (int j = 0; j < 4; ++j) {
                const float p = __expf(s[i][j] - mnew);
                s[i][j] = p;
                psum += p;
            }
            #pragma unroll
            for (int off = 8; off >= 1; off >>= 1)
                psum += __shfl_xor_sync(0xffffffffu, psum, off);
            lrun[i] += psum;
            mrun[i] = mnew;
            // store P into KPs
            #pragma unroll
            for (int j = 0; j < 4; ++j) KPs[ty * 4 + i][tx + 16 * j] = s[i][j];
        }
        __syncthreads();

        // O += P V
        #pragma unroll 8
        for (int m = 0; m < QT; ++m) {
            float pv[4], vv[4];
            #pragma unroll
            for (int i = 0; i < 4; ++i) pv[i] = KPs[ty * 4 + i][m];
            #pragma unroll
            for (int j = 0; j < 4; ++j) vv[j] = Vs[m][tx + 16 * j];
            #pragma unroll
            for (int i = 0; i < 4; ++i)
                #pragma unroll
                for (int j = 0; j < 4; ++j)
                    oacc[i][j] += pv[i] * vv[j];
        }
        __syncthreads();  // before next K/V tile overwrites smem
    }

    // Normalize and write output in [B, L, H*HD] layout
    #pragma unroll
    for (int i = 0; i < 4; ++i) {
        const float inv = 1.0f / lrun[i];
        const int  qrow = qi * QT + ty * 4 + i;
        #pragma unroll
        for (int j = 0; j < 4; ++j) {
            const int c = tx + 16 * j;
            out[((size_t)b * SEQ + qrow) * DMODEL + h * HDIM + c] = oacc[i][j] * inv;
        }
    }
}

// ---------------------------------------------------------------------------
extern "C" void kernel_launch(void* const* d_in, const int* in_sizes, int n_in,
                              void* d_out, int out_size)
{
    const float* X  = (const float*)d_in[0];
    const float* Wq = (const float*)d_in[1];
    const float* bq = (const float*)d_in[2];
    const float* Wk = (const float*)d_in[3];
    const float* bk = (const float*)d_in[4];
    const float* Wv = (const float*)d_in[5];
    const float* bv = (const float*)d_in[6];
    float* out = (float*)d_out;

    // QKV projections: grid (rows/64, cols/64, 3)
    dim3 pg((BATCH * SEQ) / 64, DMODEL / 64, 3);
    proj_kernel<<<pg, 256>>>(X, Wq, bq, Wk, bk, Wv, bv);

    // Attention: dynamic smem = 3 * 64 * 65 * 4 bytes
    const int smem_bytes = 3 * 64 * 65 * sizeof(float);
    cudaFuncSetAttribute(attn_kernel, cudaFuncAttributeMaxDynamicSharedMemorySize,
                         smem_bytes);
    dim3 ag(SEQ / QT, BATCH * NHEAD);
    attn_kernel<<<ag, 256, smem_bytes>>>(out);
}

// round 5
// speedup vs baseline: 1.5766x; 1.5766x over previous
#include <cuda_runtime.h>
#include <cuda_bf16.h>
#include <cstdint>

// Problem constants
#define BATCH 4
#define SEQ   2048
#define DMODEL 1024
#define NHEAD 16
#define HDIM  64
#define SCALE 0.25f
#define QT 64

// ---------------------------------------------------------------------------
// Static device scratch
// ---------------------------------------------------------------------------
__device__ float g_Q[(size_t)BATCH * NHEAD * SEQ * HDIM];
__device__ float g_K[(size_t)BATCH * NHEAD * SEQ * HDIM];
__device__ float g_V[(size_t)BATCH * NHEAD * SEQ * HDIM];

__device__ __nv_bfloat16 g_Xhi[(size_t)BATCH * SEQ * DMODEL];
__device__ __nv_bfloat16 g_Xlo[(size_t)BATCH * SEQ * DMODEL];
__device__ __nv_bfloat16 g_Whi[(size_t)3 * DMODEL * DMODEL];
__device__ __nv_bfloat16 g_Wlo[(size_t)3 * DMODEL * DMODEL];

// ---------------------------------------------------------------------------
// Helpers
// ---------------------------------------------------------------------------
__device__ __forceinline__ uint32_t smem_u32(const void* p) {
    uint32_t a;
    asm("{ .reg .u64 t; cvta.to.shared.u64 t, %1; cvt.u32.u64 %0, t; }"
        : "=r"(a) : "l"(p));
    return a;
}

__device__ __forceinline__ void cp16(uint32_t d, const void* s) {
    asm volatile("cp.async.cg.shared.global [%0], [%1], 16;" :: "r"(d), "l"(s) : "memory");
}
#define CP_COMMIT() asm volatile("cp.async.commit_group;" ::: "memory")
#define CP_WAIT(N)  asm volatile("cp.async.wait_group %0;" :: "n"(N) : "memory")

__device__ __forceinline__ uint32_t lds32(uint32_t a) {
    uint32_t v;
    asm volatile("ld.shared.b32 %0, [%1];" : "=r"(v) : "r"(a));
    return v;
}

// mma.sync m16n8k16 bf16 * bf16 -> f32 (baseline PTX, works on sm_103 target)
__device__ __forceinline__ void mma16816(float* c, const uint32_t* a, const uint32_t* b) {
    asm volatile(
        "mma.sync.aligned.m16n8k16.row.col.f32.bf16.bf16.f32 "
        "{%0,%1,%2,%3}, {%4,%5,%6,%7}, {%8,%9}, {%0,%1,%2,%3};"
        : "+f"(c[0]), "+f"(c[1]), "+f"(c[2]), "+f"(c[3])
        : "r"(a[0]), "r"(a[1]), "r"(a[2]), "r"(a[3]), "r"(b[0]), "r"(b[1]));
}

// Fast exp for x <= 0 on the FMA pipe (MUFU is the attention bottleneck).
// deg-6 exp2 poly, rel err ~1e-5; exponent folded in via int add.
__device__ __forceinline__ float fexp(float x) {
    x = fmaxf(x, -87.0f);
    const float y = x * 1.44269504f;
    const float fl = floorf(y);
    const float f = y - fl;
    float p = 1.5403530e-4f;
    p = fmaf(p, f, 1.3333558e-3f);
    p = fmaf(p, f, 9.6181291e-3f);
    p = fmaf(p, f, 5.5504109e-2f);
    p = fmaf(p, f, 2.4022651e-1f);
    p = fmaf(p, f, 6.9314718e-1f);
    p = fmaf(p, f, 1.0f);
    return __int_as_float(__float_as_int(p) + (((int)fl) << 23));
}

// ---------------------------------------------------------------------------
// Split fp32 -> (bf16 hi, bf16 lo)
// ---------------------------------------------------------------------------
__global__ __launch_bounds__(256) void split_kernel(
    const float* __restrict__ src,
    __nv_bfloat16* __restrict__ hi, __nv_bfloat16* __restrict__ lo)
{
    const int i = blockIdx.x * 256 + threadIdx.x;
    float4 v = ((const float4*)src)[i];
    float a[4] = {v.x, v.y, v.z, v.w};
    __nv_bfloat16 h[4], l[4];
    #pragma unroll
    for (int j = 0; j < 4; ++j) {
        h[j] = __float2bfloat16(a[j]);
        l[j] = __float2bfloat16(a[j] - __bfloat162float(h[j]));
    }
    ((__nv_bfloat162*)hi)[2 * i + 0] = __halves2bfloat162(h[0], h[1]);
    ((__nv_bfloat162*)hi)[2 * i + 1] = __halves2bfloat162(h[2], h[3]);
    ((__nv_bfloat162*)lo)[2 * i + 0] = __halves2bfloat162(l[0], l[1]);
    ((__nv_bfloat162*)lo)[2 * i + 1] = __halves2bfloat162(l[2], l[3]);
}

// ---------------------------------------------------------------------------
// mma.sync projection GEMM: C[8192x1024] = X @ W^T + bias, split-bf16 3-term.
// CTA tile 128x128, 8 warps (4x2), warp tile 32x64. kc=32 double-buffered
// cp.async. Smem rows padded to 40 bf16 (80B) -> conflict-free fragment LDS.
// Output scattered into [B, H, L, HD] fp32.
// ---------------------------------------------------------------------------
#define PITCH 40            // bf16 elements per smem row (80 bytes, 16B-aligned)
#define ARR_BYTES (128 * PITCH * 2)      // 10240
#define STG_BYTES (4 * ARR_BYTES)        // 40960 (Ahi, Alo, Bhi, Blo)
#define GEMM_SMEM (2 * STG_BYTES)        // 81920

__device__ __forceinline__ void load_stage(
    uint32_t stg, const __nv_bfloat16* __restrict__ Xh,
    const __nv_bfloat16* __restrict__ Xl,
    const __nv_bfloat16* __restrict__ Wh,
    const __nv_bfloat16* __restrict__ Wl,
    int rowBase, int colBase, int k0, int tid)
{
    #pragma unroll
    for (int it = 0; it < 8; ++it) {
        const int u = tid + it * 256;
        const int arr = it >> 1;              // 0:Ahi 1:Alo 2:Bhi 3:Blo
        const int r = (u >> 2) & 127;
        const int cc = u & 3;
        const __nv_bfloat16* src;
        if (arr == 0)      src = Xh + (size_t)(rowBase + r) * DMODEL + k0 + cc * 8;
        else if (arr == 1) src = Xl + (size_t)(rowBase + r) * DMODEL + k0 + cc * 8;
        else if (arr == 2) src = Wh + (size_t)(colBase + r) * DMODEL + k0 + cc * 8;
        else               src = Wl + (size_t)(colBase + r) * DMODEL + k0 + cc * 8;
        cp16(stg + arr * ARR_BYTES + r * (PITCH * 2) + cc * 16, src);
    }
}

__global__ __launch_bounds__(256) void gemm_kernel(
    const float* __restrict__ bq, const float* __restrict__ bk,
    const float* __restrict__ bv)
{
    extern __shared__ char smem[];
    const uint32_t sb = smem_u32(smem);
    const int tid = threadIdx.x;
    const int warp = tid >> 5;
    const int lane = tid & 31;
    const int g = lane >> 2;
    const int c = lane & 3;
    const int wm = warp >> 1;       // 0..3
    const int wn = warp & 1;        // 0..1

    const int which = blockIdx.z;
    const __nv_bfloat16* Wh = g_Whi + (size_t)which * DMODEL * DMODEL;
    const __nv_bfloat16* Wl = g_Wlo + (size_t)which * DMODEL * DMODEL;
    const float* bias = (which == 0) ? bq : (which == 1) ? bk : bv;
    float* outp = (which == 0) ? g_Q : (which == 1) ? g_K : g_V;

    const int rowBase = blockIdx.x * 128;
    const int colBase = blockIdx.y * 128;

    float acc[2][8][4] = {};

    // prologue
    load_stage(sb, g_Xhi, g_Xlo, Wh, Wl, rowBase, colBase, 0, tid);
    CP_COMMIT();

    const uint32_t aRowB = (uint32_t)(wm * 32 + g) * (PITCH * 2) + c * 4;
    const uint32_t bColB = (uint32_t)(wn * 64 + g) * (PITCH * 2) + c * 4;

    for (int sidx = 0; sidx < DMODEL / 32; ++sidx) {
        const uint32_t stg = sb + (uint32_t)(sidx & 1) * STG_BYTES;
        if (sidx + 1 < DMODEL / 32) {
            load_stage(sb + (uint32_t)((sidx + 1) & 1) * STG_BYTES,
                       g_Xhi, g_Xlo, Wh, Wl, rowBase, colBase, (sidx + 1) * 32, tid);
            CP_COMMIT();
            CP_WAIT(1);
        } else {
            CP_WAIT(0);
        }
        __syncthreads();

        #pragma unroll
        for (int kk = 0; kk < 2; ++kk) {
            const uint32_t ko = kk * 32;   // bytes: 16 bf16 per k16 step
            uint32_t ah[2][4], al[2][4], bh[8][2], bl[8][2];
            #pragma unroll
            for (int mt = 0; mt < 2; ++mt) {
                const uint32_t ba = stg + aRowB + mt * 16 * (PITCH * 2) + ko;
                ah[mt][0] = lds32(ba);
                ah[mt][1] = lds32(ba + 8 * (PITCH * 2));
                ah[mt][2] = lds32(ba + 16);
                ah[mt][3] = lds32(ba + 8 * (PITCH * 2) + 16);
                const uint32_t bal = ba + ARR_BYTES;
                al[mt][0] = lds32(bal);
                al[mt][1] = lds32(bal + 8 * (PITCH * 2));
                al[mt][2] = lds32(bal + 16);
                al[mt][3] = lds32(bal + 8 * (PITCH * 2) + 16);
            }
            #pragma unroll
            for (int nt = 0; nt < 8; ++nt) {
                const uint32_t bb = stg + 2 * ARR_BYTES + bColB + nt * 8 * (PITCH * 2) + ko;
                bh[nt][0] = lds32(bb);
                bh[nt][1] = lds32(bb + 16);
                bl[nt][0] = lds32(bb + ARR_BYTES);
                bl[nt][1] = lds32(bb + ARR_BYTES + 16);
            }
            #pragma unroll
            for (int mt = 0; mt < 2; ++mt)
                #pragma unroll
                for (int nt = 0; nt < 8; ++nt)
                    mma16816(acc[mt][nt], ah[mt], bh[nt]);
            #pragma unroll
            for (int mt = 0; mt < 2; ++mt)
                #pragma unroll
                for (int nt = 0; nt < 8; ++nt)
                    mma16816(acc[mt][nt], ah[mt], bl[nt]);
            #pragma unroll
            for (int mt = 0; mt < 2; ++mt)
                #pragma unroll
                for (int nt = 0; nt < 8; ++nt)
                    mma16816(acc[mt][nt], al[mt], bh[nt]);
        }
        __syncthreads();
    }

    // Epilogue: add bias, scatter fp32 into [B, H, L, HD]
    #pragma unroll
    for (int mt = 0; mt < 2; ++mt) {
        const int row0 = rowBase + wm * 32 + mt * 16 + g;
        #pragma unroll
        for (int nt = 0; nt < 8; ++nt) {
            const int col = colBase + wn * 64 + nt * 8 + 2 * c;
            const float bx = __ldg(&bias[col]);
            const float by = __ldg(&bias[col + 1]);
            const int h = col >> 6, hd = col & 63;
            #pragma unroll
            for (int half = 0; half < 2; ++half) {
                const int row = row0 + half * 8;
                const int b = row >> 11, s = row & 2047;
                float2 v;
                v.x = acc[mt][nt][half * 2 + 0] + bx;
                v.y = acc[mt][nt][half * 2 + 1] + by;
                *(float2*)&outp[(((size_t)b * NHEAD + h) * SEQ + s) * HDIM + hd] = v;
            }
        }
    }
}

// ---------------------------------------------------------------------------
// Flash-attention (causal, fp32, online softmax) — poly exp, scalar matmul.
// ---------------------------------------------------------------------------
__global__ __launch_bounds__(256) void attn_kernel(float* __restrict__ out)
{
    extern __shared__ float fsmem[];
    float (*Qs)[65]  = (float(*)[65])fsmem;
    float (*KPs)[65] = (float(*)[65])(fsmem + 64 * 65);
    float (*Vs)[65]  = (float(*)[65])(fsmem + 2 * 64 * 65);

    const int bh = blockIdx.y;
    const int b  = bh >> 4;
    const int h  = bh & 15;
    const int qi = (SEQ / QT - 1) - blockIdx.x;

    const float* __restrict__ Qp = g_Q + (((size_t)bh * SEQ) + (size_t)qi * QT) * HDIM;
    const float* __restrict__ Kb = g_K + (size_t)bh * SEQ * HDIM;
    const float* __restrict__ Vb = g_V + (size_t)bh * SEQ * HDIM;

    const int tid = threadIdx.x;
    const int tx = tid & 15;
    const int ty = tid >> 4;

    #pragma unroll
    for (int it = 0; it < 4; ++it) {
        const int idx = tid + 256 * it;
        const int r  = idx >> 4;
        const int cq = (idx & 15) * 4;
        float4 v = *(const float4*)(Qp + r * HDIM + cq);
        Qs[r][cq + 0] = v.x; Qs[r][cq + 1] = v.y;
        Qs[r][cq + 2] = v.z; Qs[r][cq + 3] = v.w;
    }

    float oacc[4][4] = {};
    float mrun[4], lrun[4];
    #pragma unroll
    for (int i = 0; i < 4; ++i) { mrun[i] = -1e30f; lrun[i] = 0.0f; }

    __syncthreads();

    for (int jb = 0; jb <= qi; ++jb) {
        const float* Kp = Kb + (size_t)jb * QT * HDIM;
        const float* Vp = Vb + (size_t)jb * QT * HDIM;
        #pragma unroll
        for (int it = 0; it < 4; ++it) {
            const int idx = tid + 256 * it;
            const int r  = idx >> 4;
            const int cq = (idx & 15) * 4;
            float4 kv = *(const float4*)(Kp + r * HDIM + cq);
            KPs[r][cq + 0] = kv.x; KPs[r][cq + 1] = kv.y;
            KPs[r][cq + 2] = kv.z; KPs[r][cq + 3] = kv.w;
            float4 vv = *(const float4*)(Vp + r * HDIM + cq);
            Vs[r][cq + 0] = vv.x; Vs[r][cq + 1] = vv.y;
            Vs[r][cq + 2] = vv.z; Vs[r][cq + 3] = vv.w;
        }
        __syncthreads();

        float s[4][4] = {};
        #pragma unroll 8
        for (int d = 0; d < HDIM; ++d) {
            float qv[4], kv[4];
            #pragma unroll
            for (int i = 0; i < 4; ++i) qv[i] = Qs[ty * 4 + i][d];
            #pragma unroll
            for (int j = 0; j < 4; ++j) kv[j] = KPs[tx + 16 * j][d];
            #pragma unroll
            for (int i = 0; i < 4; ++i)
                #pragma unroll
                for (int j = 0; j < 4; ++j)
                    s[i][j] += qv[i] * kv[j];
        }
        __syncthreads();

        const bool diag = (jb == qi);
        #pragma unroll
        for (int i = 0; i < 4; ++i) {
            const int r = ty * 4 + i;
            #pragma unroll
            for (int j = 0; j < 4; ++j) {
                const int col = tx + 16 * j;
                s[i][j] = (diag && col > r) ? -1e30f : s[i][j] * SCALE;
            }
        }

        #pragma unroll
        for (int i = 0; i < 4; ++i) {
            float rm = fmaxf(fmaxf(s[i][0], s[i][1]), fmaxf(s[i][2], s[i][3]));
            #pragma unroll
            for (int off = 8; off >= 1; off >>= 1)
                rm = fmaxf(rm, __shfl_xor_sync(0xffffffffu, rm, off));
            const float mnew = fmaxf(mrun[i], rm);
            const float corr = fexp(mrun[i] - mnew);
            lrun[i] *= corr;
            #pragma unroll
            for (int j = 0; j < 4; ++j) oacc[i][j] *= corr;
            float psum = 0.0f;
            #pragma unroll
            for (int j = 0; j < 4; ++j) {
                const float p = fexp(s[i][j] - mnew);
                s[i][j] = p;
                psum += p;
            }
            #pragma unroll
            for (int off = 8; off >= 1; off >>= 1)
                psum += __shfl_xor_sync(0xffffffffu, psum, off);
            lrun[i] += psum;
            mrun[i] = mnew;
            #pragma unroll
            for (int j = 0; j < 4; ++j) KPs[ty * 4 + i][tx + 16 * j] = s[i][j];
        }
        __syncthreads();

        #pragma unroll 8
        for (int m = 0; m < QT; ++m) {
            float pv[4], vv[4];
            #pragma unroll
            for (int i = 0; i < 4; ++i) pv[i] = KPs[ty * 4 + i][m];
            #pragma unroll
            for (int j = 0; j < 4; ++j) vv[j] = Vs[m][tx + 16 * j];
            #pragma unroll
            for (int i = 0; i < 4; ++i)
                #pragma unroll
                for (int j = 0; j < 4; ++j)
                    oacc[i][j] += pv[i] * vv[j];
        }
        __syncthreads();
    }

    #pragma unroll
    for (int i = 0; i < 4; ++i) {
        const float inv = 1.0f / lrun[i];
        const int  qrow = qi * QT + ty * 4 + i;
        #pragma unroll
        for (int j = 0; j < 4; ++j) {
            const int col = tx + 16 * j;
            out[((size_t)b * SEQ + qrow) * DMODEL + h * HDIM + col] = oacc[i][j] * inv;
        }
    }
}

// ---------------------------------------------------------------------------
extern "C" void kernel_launch(void* const* d_in, const int* in_sizes, int n_in,
                              void* d_out, int out_size)
{
    const float* X  = (const float*)d_in[0];
    const float* Wq = (const float*)d_in[1];
    const float* bq = (const float*)d_in[2];
    const float* Wk = (const float*)d_in[3];
    const float* bk = (const float*)d_in[4];
    const float* Wv = (const float*)d_in[5];
    const float* bv = (const float*)d_in[6];
    float* out = (float*)d_out;

    __nv_bfloat16 *xhi, *xlo, *whi, *wlo;
    cudaGetSymbolAddress((void**)&xhi, g_Xhi);
    cudaGetSymbolAddress((void**)&xlo, g_Xlo);
    cudaGetSymbolAddress((void**)&whi, g_Whi);
    cudaGetSymbolAddress((void**)&wlo, g_Wlo);

    const int xN4 = BATCH * SEQ * DMODEL / 4;
    const int wN4 = DMODEL * DMODEL / 4;
    split_kernel<<<xN4 / 256, 256>>>(X, xhi, xlo);
    split_kernel<<<wN4 / 256, 256>>>(Wq, whi + 0 * (size_t)DMODEL * DMODEL,
                                         wlo + 0 * (size_t)DMODEL * DMODEL);
    split_kernel<<<wN4 / 256, 256>>>(Wk, whi + 1 * (size_t)DMODEL * DMODEL,
                                         wlo + 1 * (size_t)DMODEL * DMODEL);
    split_kernel<<<wN4 / 256, 256>>>(Wv, whi + 2 * (size_t)DMODEL * DMODEL,
                                         wlo + 2 * (size_t)DMODEL * DMODEL);

    cudaFuncSetAttribute(gemm_kernel, cudaFuncAttributeMaxDynamicSharedMemorySize,
                         GEMM_SMEM);
    dim3 gg((BATCH * SEQ) / 128, DMODEL / 128, 3);
    gemm_kernel<<<gg, 256, GEMM_SMEM>>>(bq, bk, bv);

    const int smem_bytes = 3 * 64 * 65 * sizeof(float);
    cudaFuncSetAttribute(attn_kernel, cudaFuncAttributeMaxDynamicSharedMemorySize,
                         smem_bytes);
    dim3 ag(SEQ / QT, BATCH * NHEAD);
    attn_kernel<<<ag, 256, smem_bytes>>>(out);
}

// round 7
// speedup vs baseline: 3.0543x; 1.9373x over previous
#include <cuda_runtime.h>
#include <cuda_bf16.h>
#include <cstdint>

// Problem constants
#define BATCH 4
#define SEQ   2048
#define DMODEL 1024
#define NHEAD 16
#define HDIM  64
#define SCALE 0.25f

// ---------------------------------------------------------------------------
// Static device scratch
// ---------------------------------------------------------------------------
#define QKV_ELEMS ((size_t)BATCH * NHEAD * SEQ * HDIM)
__device__ __nv_bfloat16 g_Qhi[QKV_ELEMS];
__device__ __nv_bfloat16 g_Qlo[QKV_ELEMS];
__device__ __nv_bfloat16 g_Khi[QKV_ELEMS];
__device__ __nv_bfloat16 g_Klo[QKV_ELEMS];
__device__ __nv_bfloat16 g_Vthi[QKV_ELEMS];   // [B,H,HD,L] (transposed)
__device__ __nv_bfloat16 g_Vtlo[QKV_ELEMS];

__device__ __nv_bfloat16 g_Xhi[(size_t)BATCH * SEQ * DMODEL];
__device__ __nv_bfloat16 g_Xlo[(size_t)BATCH * SEQ * DMODEL];
__device__ __nv_bfloat16 g_Whi[(size_t)3 * DMODEL * DMODEL];
__device__ __nv_bfloat16 g_Wlo[(size_t)3 * DMODEL * DMODEL];

// ---------------------------------------------------------------------------
// Helpers
// ---------------------------------------------------------------------------
__device__ __forceinline__ uint32_t smem_u32(const void* p) {
    uint32_t a;
    asm("{ .reg .u64 t; cvta.to.shared.u64 t, %1; cvt.u32.u64 %0, t; }"
        : "=r"(a) : "l"(p));
    return a;
}

__device__ __forceinline__ void cp16(uint32_t d, const void* s) {
    asm volatile("cp.async.cg.shared.global [%0], [%1], 16;" :: "r"(d), "l"(s) : "memory");
}
#define CP_COMMIT() asm volatile("cp.async.commit_group;" ::: "memory")
#define CP_WAIT(N)  asm volatile("cp.async.wait_group %0;" :: "n"(N) : "memory")

__device__ __forceinline__ uint32_t lds32(uint32_t a) {
    uint32_t v;
    asm volatile("ld.shared.b32 %0, [%1];" : "=r"(v) : "r"(a));
    return v;
}

__device__ __forceinline__ void mma16816(float* c, const uint32_t* a, const uint32_t* b) {
    asm volatile(
        "mma.sync.aligned.m16n8k16.row.col.f32.bf16.bf16.f32 "
        "{%0,%1,%2,%3}, {%4,%5,%6,%7}, {%8,%9}, {%0,%1,%2,%3};"
        : "+f"(c[0]), "+f"(c[1]), "+f"(c[2]), "+f"(c[3])
        : "r"(a[0]), "r"(a[1]), "r"(a[2]), "r"(a[3]), "r"(b[0]), "r"(b[1]));
}

// Fast exp on the FMA pipe (x <= 0), rel err ~1e-5.
__device__ __forceinline__ float fexp(float x) {
    x = fmaxf(x, -87.0f);
    const float y = x * 1.44269504f;
    const float fl = floorf(y);
    const float f = y - fl;
    float p = 1.5403530e-4f;
    p = fmaf(p, f, 1.3333558e-3f);
    p = fmaf(p, f, 9.6181291e-3f);
    p = fmaf(p, f, 5.5504109e-2f);
    p = fmaf(p, f, 2.4022651e-1f);
    p = fmaf(p, f, 6.9314718e-1f);
    p = fmaf(p, f, 1.0f);
    return __int_as_float(__float_as_int(p) + (((int)fl) << 23));
}

__device__ __forceinline__ uint32_t pack_bf2(float x, float y) {
    __nv_bfloat162 t = __halves2bfloat162(__float2bfloat16(x), __float2bfloat16(y));
    return *(uint32_t*)&t;
}

// ---------------------------------------------------------------------------
// Split fp32 -> (bf16 hi, bf16 lo)
// ---------------------------------------------------------------------------
__global__ __launch_bounds__(256) void split_kernel(
    const float* __restrict__ src,
    __nv_bfloat16* __restrict__ hi, __nv_bfloat16* __restrict__ lo)
{
    const int i = blockIdx.x * 256 + threadIdx.x;
    float4 v = ((const float4*)src)[i];
    float a[4] = {v.x, v.y, v.z, v.w};
    __nv_bfloat16 h[4], l[4];
    #pragma unroll
    for (int j = 0; j < 4; ++j) {
        h[j] = __float2bfloat16(a[j]);
        l[j] = __float2bfloat16(a[j] - __bfloat162float(h[j]));
    }
    ((__nv_bfloat162*)hi)[2 * i + 0] = __halves2bfloat162(h[0], h[1]);
    ((__nv_bfloat162*)hi)[2 * i + 1] = __halves2bfloat162(h[2], h[3]);
    ((__nv_bfloat162*)lo)[2 * i + 0] = __halves2bfloat162(l[0], l[1]);
    ((__nv_bfloat162*)lo)[2 * i + 1] = __halves2bfloat162(l[2], l[3]);
}

// ---------------------------------------------------------------------------
// mma.sync projection GEMM: C = X @ W^T + bias, split-bf16 3-term.
// Epilogue emits bf16 hi/lo: Q,K in [B,H,L,HD]; V transposed [B,H,HD,L].
// ---------------------------------------------------------------------------
#define PITCH 40
#define ARR_BYTES (128 * PITCH * 2)
#define STG_BYTES (4 * ARR_BYTES)
#define GEMM_SMEM (2 * STG_BYTES)

__device__ __forceinline__ void load_stage(
    uint32_t stg, const __nv_bfloat16* __restrict__ Xh,
    const __nv_bfloat16* __restrict__ Xl,
    const __nv_bfloat16* __restrict__ Wh,
    const __nv_bfloat16* __restrict__ Wl,
    int rowBase, int colBase, int k0, int tid)
{
    #pragma unroll
    for (int it = 0; it < 8; ++it) {
        const int u = tid + it * 256;
        const int arr = it >> 1;
        const int r = (u >> 2) & 127;
        const int cc = u & 3;
        const __nv_bfloat16* src;
        if (arr == 0)      src = Xh + (size_t)(rowBase + r) * DMODEL + k0 + cc * 8;
        else if (arr == 1) src = Xl + (size_t)(rowBase + r) * DMODEL + k0 + cc * 8;
        else if (arr == 2) src = Wh + (size_t)(colBase + r) * DMODEL + k0 + cc * 8;
        else               src = Wl + (size_t)(colBase + r) * DMODEL + k0 + cc * 8;
        cp16(stg + arr * ARR_BYTES + r * (PITCH * 2) + cc * 16, src);
    }
}

__global__ __launch_bounds__(256) void gemm_kernel(
    const float* __restrict__ bq, const float* __restrict__ bk,
    const float* __restrict__ bv)
{
    extern __shared__ char smem[];
    const uint32_t sb = smem_u32(smem);
    const int tid = threadIdx.x;
    const int warp = tid >> 5;
    const int lane = tid & 31;
    const int g = lane >> 2;
    const int c = lane & 3;
    const int wm = warp >> 1;
    const int wn = warp & 1;

    const int which = blockIdx.z;
    const __nv_bfloat16* Wh = g_Whi + (size_t)which * DMODEL * DMODEL;
    const __nv_bfloat16* Wl = g_Wlo + (size_t)which * DMODEL * DMODEL;
    const float* bias = (which == 0) ? bq : (which == 1) ? bk : bv;
    __nv_bfloat16* oh = (which == 0) ? g_Qhi : (which == 1) ? g_Khi : g_Vthi;
    __nv_bfloat16* ol = (which == 0) ? g_Qlo : (which == 1) ? g_Klo : g_Vtlo;

    const int rowBase = blockIdx.x * 128;
    const int colBase = blockIdx.y * 128;

    float acc[2][8][4] = {};

    load_stage(sb, g_Xhi, g_Xlo, Wh, Wl, rowBase, colBase, 0, tid);
    CP_COMMIT();

    const uint32_t aRowB = (uint32_t)(wm * 32 + g) * (PITCH * 2) + c * 4;
    const uint32_t bColB = (uint32_t)(wn * 64 + g) * (PITCH * 2) + c * 4;

    for (int sidx = 0; sidx < DMODEL / 32; ++sidx) {
        const uint32_t stg = sb + (uint32_t)(sidx & 1) * STG_BYTES;
        if (sidx + 1 < DMODEL / 32) {
            load_stage(sb + (uint32_t)((sidx + 1) & 1) * STG_BYTES,
                       g_Xhi, g_Xlo, Wh, Wl, rowBase, colBase, (sidx + 1) * 32, tid);
            CP_COMMIT();
            CP_WAIT(1);
        } else {
            CP_WAIT(0);
        }
        __syncthreads();

        #pragma unroll
        for (int kk = 0; kk < 2; ++kk) {
            const uint32_t ko = kk * 32;
            uint32_t ah[2][4], al[2][4], bh[8][2], bl[8][2];
            #pragma unroll
            for (int mt = 0; mt < 2; ++mt) {
                const uint32_t ba = stg + aRowB + mt * 16 * (PITCH * 2) + ko;
                ah[mt][0] = lds32(ba);
                ah[mt][1] = lds32(ba + 8 * (PITCH * 2));
                ah[mt][2] = lds32(ba + 16);
                ah[mt][3] = lds32(ba + 8 * (PITCH * 2) + 16);
                const uint32_t bal = ba + ARR_BYTES;
                al[mt][0] = lds32(bal);
                al[mt][1] = lds32(bal + 8 * (PITCH * 2));
                al[mt][2] = lds32(bal + 16);
                al[mt][3] = lds32(bal + 8 * (PITCH * 2) + 16);
            }
            #pragma unroll
            for (int nt = 0; nt < 8; ++nt) {
                const uint32_t bb = stg + 2 * ARR_BYTES + bColB + nt * 8 * (PITCH * 2) + ko;
                bh[nt][0] = lds32(bb);
                bh[nt][1] = lds32(bb + 16);
                bl[nt][0] = lds32(bb + ARR_BYTES);
                bl[nt][1] = lds32(bb + ARR_BYTES + 16);
            }
            #pragma unroll
            for (int mt = 0; mt < 2; ++mt)
                #pragma unroll
                for (int nt = 0; nt < 8; ++nt)
                    mma16816(acc[mt][nt], ah[mt], bh[nt]);
            #pragma unroll
            for (int mt = 0; mt < 2; ++mt)
                #pragma unroll
                for (int nt = 0; nt < 8; ++nt)
                    mma16816(acc[mt][nt], ah[mt], bl[nt]);
            #pragma unroll
            for (int mt = 0; mt < 2; ++mt)
                #pragma unroll
                for (int nt = 0; nt < 8; ++nt)
                    mma16816(acc[mt][nt], al[mt], bh[nt]);
        }
        __syncthreads();
    }

    // Epilogue: bias add, fp32 -> bf16 hi/lo, scatter
    #pragma unroll
    for (int mt = 0; mt < 2; ++mt) {
        const int row0 = rowBase + wm * 32 + mt * 16 + g;
        #pragma unroll
        for (int nt = 0; nt < 8; ++nt) {
            const int col = colBase + wn * 64 + nt * 8 + 2 * c;
            const float bx = __ldg(&bias[col]);
            const float by = __ldg(&bias[col + 1]);
            const int h = col >> 6, hd = col & 63;
            #pragma unroll
            for (int half = 0; half < 2; ++half) {
                const int row = row0 + half * 8;
                const int b = row >> 11, s = row & 2047;
                const float vx = acc[mt][nt][half * 2 + 0] + bx;
                const float vy = acc[mt][nt][half * 2 + 1] + by;
                const __nv_bfloat16 hx = __float2bfloat16(vx);
                const __nv_bfloat16 hy = __float2bfloat16(vy);
                const __nv_bfloat16 lx = __float2bfloat16(vx - __bfloat162float(hx));
                const __nv_bfloat16 ly = __float2bfloat16(vy - __bfloat162float(hy));
                if (which < 2) {
                    const size_t o = (((size_t)b * NHEAD + h) * SEQ + s) * HDIM + hd;
                    *(__nv_bfloat162*)&oh[o] = __halves2bfloat162(hx, hy);
                    *(__nv_bfloat162*)&ol[o] = __halves2bfloat162(lx, ly);
                } else {
                    const size_t o = (((size_t)b * NHEAD + h) * HDIM + hd) * SEQ + s;
                    oh[o] = hx; oh[o + SEQ] = hy;
                    ol[o] = lx; ol[o + SEQ] = ly;
                }
            }
        }
    }
}

// ---------------------------------------------------------------------------
// Tensor-core flash attention (causal). CTA = 64 q-rows, 4 warps (m16 each).
// S and P·V via mma.sync with split-bf16 3-term; P stays in registers.
// ---------------------------------------------------------------------------
#define AP2 144                 // smem row pitch in bytes (72 bf16)
#define TILEB (64 * AP2)        // 9216 per array
#define KHI_O 0
#define KLO_O TILEB
#define VHI_O (2 * TILEB)
#define VLO_O (3 * TILEB)
#define ASTGB (4 * TILEB)       // 36864 per stage
#define ATT_SMEM (2 * ASTGB)    // 73728

__device__ __forceinline__ void load_kv_tile(uint32_t stg, int bh, int key0, int tid)
{
    const __nv_bfloat16* kh = g_Khi + ((size_t)bh * SEQ + key0) * HDIM;
    const __nv_bfloat16* kl = g_Klo + ((size_t)bh * SEQ + key0) * HDIM;
    const __nv_bfloat16* vh = g_Vthi + (size_t)bh * HDIM * SEQ + key0;
    const __nv_bfloat16* vl = g_Vtlo + (size_t)bh * HDIM * SEQ + key0;
    #pragma unroll
    for (int it = 0; it < 4; ++it) {
        const int u = tid + it * 128;
        const int r = u >> 3, cc = u & 7;
        cp16(stg + KHI_O + r * AP2 + cc * 16, kh + r * HDIM + cc * 8);
        cp16(stg + KLO_O + r * AP2 + cc * 16, kl + r * HDIM + cc * 8);
        cp16(stg + VHI_O + r * AP2 + cc * 16, vh + (size_t)r * SEQ + cc * 8);
        cp16(stg + VLO_O + r * AP2 + cc * 16, vl + (size_t)r * SEQ + cc * 8);
    }
}

__global__ __launch_bounds__(128) void attn_kernel(float* __restrict__ out)
{
    extern __shared__ char smemc[];
    const uint32_t sb = smem_u32(smemc);
    const int tid = threadIdx.x;
    const int warp = tid >> 5;
    const int lane = tid & 31;
    const int g = lane >> 2;
    const int c = lane & 3;
    const int moff = warp * 16;

    const int bh = blockIdx.y;
    const int b = bh >> 4;
    const int h = bh & 15;
    const int qi = (SEQ / 64 - 1) - blockIdx.x;   // heavy q-tiles first

    // --- Stage Q (hi/lo) into stage-1 K slots, and tile 0 into stage 0 ---
    {
        const __nv_bfloat16* qh = g_Qhi + ((size_t)bh * SEQ + (size_t)qi * 64) * HDIM;
        const __nv_bfloat16* ql = g_Qlo + ((size_t)bh * SEQ + (size_t)qi * 64) * HDIM;
        #pragma unroll
        for (int it = 0; it < 4; ++it) {
            const int u = tid + it * 128;
            const int r = u >> 3, cc = u & 7;
            cp16(sb + ASTGB + KHI_O + r * AP2 + cc * 16, qh + r * HDIM + cc * 8);
            cp16(sb + ASTGB + KLO_O + r * AP2 + cc * 16, ql + r * HDIM + cc * 8);
        }
        CP_COMMIT();
        load_kv_tile(sb, bh, 0, tid);
        CP_COMMIT();
    }

    // --- Read persistent Q fragments ---
    uint32_t qhi[4][4], qlo[4][4];
    CP_WAIT(1);
    __syncthreads();
    {
        const uint32_t qb = sb + ASTGB + KHI_O + (uint32_t)(moff + g) * AP2 + c * 4;
        #pragma unroll
        for (int kt = 0; kt < 4; ++kt) {
            qhi[kt][0] = lds32(qb + kt * 32);
            qhi[kt][1] = lds32(qb + kt * 32 + 8 * AP2);
            qhi[kt][2] = lds32(qb + kt * 32 + 16);
            qhi[kt][3] = lds32(qb + kt * 32 + 8 * AP2 + 16);
            qlo[kt][0] = lds32(qb + TILEB + kt * 32);
            qlo[kt][1] = lds32(qb + TILEB + kt * 32 + 8 * AP2);
            qlo[kt][2] = lds32(qb + TILEB + kt * 32 + 16);
            qlo[kt][3] = lds32(qb + TILEB + kt * 32 + 8 * AP2 + 16);
        }
    }
    __syncthreads();   // Q slots free for pipeline reuse

    float O[8][4] = {};
    float m[2] = {-1e30f, -1e30f};
    float l[2] = {0.0f, 0.0f};

    for (int jb = 0; jb <= qi; ++jb) {
        const uint32_t stg = sb + (uint32_t)(jb & 1) * ASTGB;
        if (jb < qi) {
            load_kv_tile(sb + (uint32_t)((jb + 1) & 1) * ASTGB, bh, (jb + 1) * 64, tid);
            CP_COMMIT();
            CP_WAIT(1);
        } else {
            CP_WAIT(0);
        }
        __syncthreads();

        // ----- S = Q K^T (3-term split) -----
        float S[8][4] = {};
        #pragma unroll
        for (int kt = 0; kt < 4; ++kt) {
            uint32_t bhf[8][2], blf[8][2];
            const uint32_t kb = stg + KHI_O + (uint32_t)g * AP2 + kt * 32 + c * 4;
            #pragma unroll
            for (int nt = 0; nt < 8; ++nt) {
                const uint32_t a0 = kb + nt * 8 * AP2;
                bhf[nt][0] = lds32(a0);
                bhf[nt][1] = lds32(a0 + 16);
                blf[nt][0] = lds32(a0 + TILEB);
                blf[nt][1] = lds32(a0 + TILEB + 16);
            }
            #pragma unroll
            for (int nt = 0; nt < 8; ++nt) mma16816(S[nt], qhi[kt], bhf[nt]);
            #pragma unroll
            for (int nt = 0; nt < 8; ++nt) mma16816(S[nt], qhi[kt], blf[nt]);
            #pragma unroll
            for (int nt = 0; nt < 8; ++nt) mma16816(S[nt], qlo[kt], bhf[nt]);
        }

        // ----- scale + causal mask -----
        const bool diag = (jb == qi);
        #pragma unroll
        for (int nt = 0; nt < 8; ++nt) {
            #pragma unroll
            for (int e = 0; e < 4; ++e) {
                float v = S[nt][e] * SCALE;
                if (diag) {
                    const int col = nt * 8 + 2 * c + (e & 1);
                    const int row = moff + g + ((e >> 1) << 3);
                    if (col > row) v = -1e30f;
                }
                S[nt][e] = v;
            }
        }

        // ----- online softmax (rows g, g+8) -----
        float rowm[2] = {-1e30f, -1e30f};
        #pragma unroll
        for (int nt = 0; nt < 8; ++nt) {
            rowm[0] = fmaxf(rowm[0], fmaxf(S[nt][0], S[nt][1]));
            rowm[1] = fmaxf(rowm[1], fmaxf(S[nt][2], S[nt][3]));
        }
        #pragma unroll
        for (int r = 0; r < 2; ++r) {
            rowm[r] = fmaxf(rowm[r], __shfl_xor_sync(0xffffffffu, rowm[r], 1));
            rowm[r] = fmaxf(rowm[r], __shfl_xor_sync(0xffffffffu, rowm[r], 2));
        }
        float corr[2];
        #pragma unroll
        for (int r = 0; r < 2; ++r) {
            const float mnew = fmaxf(m[r], rowm[r]);
            corr[r] = fexp(m[r] - mnew);
            l[r] *= corr[r];
            m[r] = mnew;
        }
        #pragma unroll
        for (int nt = 0; nt < 8; ++nt) {
            O[nt][0] *= corr[0]; O[nt][1] *= corr[0];
            O[nt][2] *= corr[1]; O[nt][3] *= corr[1];
        }
        float psum[2] = {0.0f, 0.0f};
        #pragma unroll
        for (int nt = 0; nt < 8; ++nt) {
            #pragma unroll
            for (int e = 0; e < 4; ++e) {
                const float p = fexp(S[nt][e] - m[e >> 1]);
                S[nt][e] = p;
                psum[e >> 1] += p;
            }
        }
        #pragma unroll
        for (int r = 0; r < 2; ++r) {
            psum[r] += __shfl_xor_sync(0xffffffffu, psum[r], 1);
            psum[r] += __shfl_xor_sync(0xffffffffu, psum[r], 2);
            l[r] += psum[r];
        }

        // ----- split P into bf16 hi/lo A-fragments (register-only) -----
        uint32_t phi[4][4], plo[4][4];
        #pragma unroll
        for (int t = 0; t < 8; ++t) {
            const int kt = t >> 1;
            const int sl = (t & 1) << 1;   // 0 or 2
            float h01x = __bfloat162float(__float2bfloat16(S[t][0]));
            float h01y = __bfloat162float(__float2bfloat16(S[t][1]));
            float h23x = __bfloat162float(__float2bfloat16(S[t][2]));
            float h23y = __bfloat162float(__float2bfloat16(S[t][3]));
            phi[kt][sl + 0] = pack_bf2(h01x, h01y);
            phi[kt][sl + 1] = pack_bf2(h23x, h23y);
            plo[kt][sl + 0] = pack_bf2(S[t][0] - h01x, S[t][1] - h01y);
            plo[kt][sl + 1] = pack_bf2(S[t][2] - h23x, S[t][3] - h23y);
        }
        // reorder: phi[kt] = {tile2kt.c01, tile2kt.c23, tile2kt+1.c01, tile2kt+1.c23}
        // (t even -> slots 0,1; t odd -> slots 2,3) -- handled by sl above.

        // ----- O += P V (3-term split) -----
        #pragma unroll
        for (int kt = 0; kt < 4; ++kt) {
            uint32_t vhf[8][2], vlf[8][2];
            const uint32_t vb = stg + VHI_O + (uint32_t)g * AP2 + kt * 32 + c * 4;
            #pragma unroll
            for (int nt = 0; nt < 8; ++nt) {
                const uint32_t a0 = vb + nt * 8 * AP2;
                vhf[nt][0] = lds32(a0);
                vhf[nt][1] = lds32(a0 + 16);
                vlf[nt][0] = lds32(a0 + TILEB);
                vlf[nt][1] = lds32(a0 + TILEB + 16);
            }
            #pragma unroll
            for (int nt = 0; nt < 8; ++nt) mma16816(O[nt], phi[kt], vhf[nt]);
            #pragma unroll
            for (int nt = 0; nt < 8; ++nt) mma16816(O[nt], phi[kt], vlf[nt]);
            #pragma unroll
            for (int nt = 0; nt < 8; ++nt) mma16816(O[nt], plo[kt], vhf[nt]);
        }
        __syncthreads();
    }

    // ----- normalize + write out [B, L, D] -----
    const float inv0 = 1.0f / l[0];
    const float inv1 = 1.0f / l[1];
    const int row0 = qi * 64 + moff + g;
    #pragma unroll
    for (int nt = 0; nt < 8; ++nt) {
        const int col = h * HDIM + nt * 8 + 2 * c;
        float2 v0 = {O[nt][0] * inv0, O[nt][1] * inv0};
        float2 v1 = {O[nt][2] * inv1, O[nt][3] * inv1};
        *(float2*)&out[((size_t)b * SEQ + row0) * DMODEL + col] = v0;
        *(float2*)&out[((size_t)b * SEQ + row0 + 8) * DMODEL + col] = v1;
    }
}

// ---------------------------------------------------------------------------
extern "C" void kernel_launch(void* const* d_in, const int* in_sizes, int n_in,
                              void* d_out, int out_size)
{
    const float* X  = (const float*)d_in[0];
    const float* Wq = (const float*)d_in[1];
    const float* bq = (const float*)d_in[2];
    const float* Wk = (const float*)d_in[3];
    const float* bk = (const float*)d_in[4];
    const float* Wv = (const float*)d_in[5];
    const float* bv = (const float*)d_in[6];
    float* out = (float*)d_out;

    __nv_bfloat16 *xhi, *xlo, *whi, *wlo;
    cudaGetSymbolAddress((void**)&xhi, g_Xhi);
    cudaGetSymbolAddress((void**)&xlo, g_Xlo);
    cudaGetSymbolAddress((void**)&whi, g_Whi);
    cudaGetSymbolAddress((void**)&wlo, g_Wlo);

    const int xN4 = BATCH * SEQ * DMODEL / 4;
    const int wN4 = DMODEL * DMODEL / 4;
    split_kernel<<<xN4 / 256, 256>>>(X, xhi, xlo);
    split_kernel<<<wN4 / 256, 256>>>(Wq, whi + 0 * (size_t)DMODEL * DMODEL,
                                         wlo + 0 * (size_t)DMODEL * DMODEL);
    split_kernel<<<wN4 / 256, 256>>>(Wk, whi + 1 * (size_t)DMODEL * DMODEL,
                                         wlo + 1 * (size_t)DMODEL * DMODEL);
    split_kernel<<<wN4 / 256, 256>>>(Wv, whi + 2 * (size_t)DMODEL * DMODEL,
                                         wlo + 2 * (size_t)DMODEL * DMODEL);

    cudaFuncSetAttribute(gemm_kernel, cudaFuncAttributeMaxDynamicSharedMemorySize,
                         GEMM_SMEM);
    dim3 gg((BATCH * SEQ) / 128, DMODEL / 128, 3);
    gemm_kernel<<<gg, 256, GEMM_SMEM>>>(bq, bk, bv);

    cudaFuncSetAttribute(attn_kernel, cudaFuncAttributeMaxDynamicSharedMemorySize,
                         ATT_SMEM);
    dim3 ag(SEQ / 64, BATCH * NHEAD);
    attn_kernel<<<ag, 128, ATT_SMEM>>>(out);
}